// round 11
// baseline (speedup 1.0000x reference)
#include <cuda_runtime.h>
#include <math.h>

// Problem constants (fixed by the reference)
#define BB 4096
#define TT 200
#define CC 38
#define SS 30
#define FULLMASK 0xffffffffu
#define CTC_BLOCKS 512            // 4096 warps = 1 per sample
#define KL_BLOCKS  15360          // BB*SS/8
#define LN2 0.6931471805599453

// Scratch (no cudaMalloc allowed)
__device__ float g_ctc[BB];         // final per-sample nll/tl
__device__ float g_klb[KL_BLOCKS];  // per-block KL partial sums

// ---------------------------------------------------------------------------
// fp64 fallback (R1/R4-proven numerics): full fp64 CTC forward including its
// own softmax-denominator accumulation. Whole warp participates. Rare.
// Returns final nll (zero_infinity applied).
// ---------------------------------------------------------------------------
__device__ __noinline__ float ctc_fp64(
    const float* __restrict__ xp, const int* __restrict__ target,
    int b, int il, int tl)
{
    const int lane = threadIdx.x & 31;
    int tg  = (lane < SS) ? target[b * SS + lane] : 1;
    int tgp = __shfl_up_sync(FULLMASK, tg, 1);
    const bool skip = (lane == 0 || tg != tgp);
    const bool hi   = tg >= 32;
    const int  tgB  = tg - 32;

    double ae = (lane == 0) ? 1.0 : 0.0;
    double ao = 0.0;
    double sumLogD = 0.0;

    for (int t = 0; t < il; ++t) {
        const float* r = xp + (size_t)t * CC;
        float x1 = r[lane];
        float x2 = (lane < 6) ? r[32 + lane] : -1e30f;
        float e1 = __expf(x1 - 2.0f);
        float e2 = __expf(x2 - 2.0f);
        float D = e1 + e2;
#pragma unroll
        for (int o = 16; o > 0; o >>= 1) D += __shfl_xor_sync(FULLMASK, D, o);
        sumLogD += (double)__logf(D);
        float pb  = __shfl_sync(FULLMASK, e1, 0);
        float plA = __shfl_sync(FULLMASK, e1, tg);
        float plB = __shfl_sync(FULLMASK, e2, tgB);
        float pl  = hi ? plB : plA;
        double op = __shfl_up_sync(FULLMASK, ao, 1);
        if (lane == 0) op = 0.0;
        double ne = (ae + op) * (double)pb;
        double no = (ao + ae + (skip ? op : 0.0)) * (double)pl;
        ae = (lane <= 30) ? ne : 0.0;
        ao = (lane < 30) ? no : 0.0;
    }
    double aev = __shfl_sync(FULLMASK, ae, tl);
    double aov = __shfl_sync(FULLMASK, ao, tl - 1);
    double s = aev + aov;
    float nll = 0.0f;
    if (s > 0.0) {
        double lg = log(s) - sumLogD;
        nll = (float)(-lg);
        if (nll > 1e8f) nll = 0.0f;
    }
    return nll;
}

// ---------------------------------------------------------------------------
// Integrated CTC warp: one warp per sample reads x ONCE (lane-strided full
// rows), computes the softmax denominator product (off the alpha chain) AND
// the beta-form recursion in the same pass.
//  - lane c holds class c (e1) and class 32+c for c<6 (e2)  -> D butterfly
//  - recursion lanes: lane i in 1..30 holds states 2(i-1), 2(i-1)+1;
//    lane 0 is a constant-zero shfl boundary; lane 31 holds even state 60.
//  - beta = alpha / prod exp(x0-2): even update is a pure add, odd multiplier
//    exp(x_tg - x0) = ONE chain MUFU per step.
//  - deferred power-of-2 renorm every 8 steps (stale max is exactly correct).
// ---------------------------------------------------------------------------
__device__ __forceinline__ void ctc_body(
    const float* __restrict__ x, const int* __restrict__ target,
    const int* __restrict__ ilen, const int* __restrict__ tlen, int b)
{
    const int lane = threadIdx.x & 31;
    const bool valid = (lane >= 1 && lane <= SS);

    int tg  = valid ? target[b * SS + (lane - 1)] : 1;
    int tgp = __shfl_up_sync(FULLMASK, tg, 1);
    const float skipf = (lane == 1 || tg != tgp) ? 1.0f : 0.0f;
    const bool hi  = tg >= 32;
    const int  tgB = tg - 32;

    const int il = ilen[b];
    const int tl = tlen[b];
    const float* xp = x + (size_t)b * TT * CC;

    float ae = (lane == 1) ? 1.0f : 0.0f;   // beta[2(lane-1)]
    float ao = 0.0f;                        // beta[2(lane-1)+1]
    int   Esum = 0;                         // true beta = stored * 2^Esum
    float bs = 0.0f;                        // sum of x0 (shift applied at end)
    float P  = 1.0f;                        // product of row denominators
    int   Le = 0;                           // stripped exponent of P

    auto step = [&](float x1v, float x2v) {
        float e1 = __expf(x1v - 2.0f);
        float e2 = __expf(x2v - 2.0f);       // lanes>=6 fed -1e30 -> 0
        float part = e1 + e2;
#pragma unroll
        for (int o = 16; o > 0; o >>= 1)
            part += __shfl_xor_sync(FULLMASK, part, o);
        P *= part;                           // off-chain denominator product
        float x0  = __shfl_sync(FULLMASK, x1v, 0);
        float xtA = __shfl_sync(FULLMASK, x1v, tg);
        float xtB = __shfl_sync(FULLMASK, x2v, tgB);
        float d = valid ? ((hi ? xtB : xtA) - x0) : -1e30f;
        float e = __expf(d);
        bs += x0;
        float op = __shfl_up_sync(FULLMASK, ao, 1);  // lane0's own ao = 0
        float v  = ae + ao;
        ae = ae + op;
        ao = fmaf(skipf, op, v) * e;
    };
    auto strip = [&]() {          // strip P's exponent (all lanes identical)
        unsigned pb = __float_as_uint(P);
        Le += (int)(pb >> 23) - 127;
        P = __uint_as_float((pb & 0x807fffffu) | 0x3f800000u);
    };
    auto apply = [&](float m) {   // warp-uniform 2^k rescale, center 2^30
        unsigned mb = __float_as_uint(m);
        if (mb >= 0x00800000u && mb < 0x7f800000u) {
            int e = (int)(mb >> 23) - 127;
            int k = 30 - e;
            k = (k > 127) ? 127 : (k < -126 ? -126 : k);
            float sc = __uint_as_float((unsigned)(127 + k) << 23);
            ae *= sc; ao *= sc;
            Esum -= k;
        }
    };

    if (il == TT) {
        // Groups of 4 rows, one group of loads in flight ahead (8 loads MLP).
        float cx1[4], cx2[4];
#pragma unroll
        for (int i = 0; i < 4; ++i) {
            cx1[i] = xp[i * CC + lane];
            cx2[i] = (lane < 6) ? xp[i * CC + 32 + lane] : -1e30f;
        }
        float m = 0.0f;
        for (int g = 0; g < TT / 4; ++g) {
            float nx1[4], nx2[4];
            if (g + 1 < TT / 4) {
                const float* np = xp + (size_t)(g + 1) * 4 * CC;
#pragma unroll
                for (int i = 0; i < 4; ++i) {
                    nx1[i] = np[i * CC + lane];
                    nx2[i] = (lane < 6) ? np[i * CC + 32 + lane] : -1e30f;
                }
            } else {
#pragma unroll
                for (int i = 0; i < 4; ++i) { nx1[i] = -1e30f; nx2[i] = -1e30f; }
            }
            if ((g & 1) == 0) {
                step(cx1[0], cx2[0]);
                step(cx1[1], cx2[1]);
                step(cx1[2], cx2[2]);
                step(cx1[3], cx2[3]);
                m = fmaxf(ae, ao);            // measure; reduce next group
            } else {
                step(cx1[0], cx2[0]);
                m = fmaxf(m, __shfl_xor_sync(FULLMASK, m, 16));
                step(cx1[1], cx2[1]);
                m = fmaxf(m, __shfl_xor_sync(FULLMASK, m, 8));
                step(cx1[2], cx2[2]);
                m = fmaxf(m, __shfl_xor_sync(FULLMASK, m, 4));
                step(cx1[3], cx2[3]);
                m = fmaxf(m, __shfl_xor_sync(FULLMASK, m, 2));
                m = fmaxf(m, __shfl_xor_sync(FULLMASK, m, 1));
                apply(m);                     // renorm every 8 steps
                strip();                      // P exponent strip every 8 rows
            }
#pragma unroll
            for (int i = 0; i < 4; ++i) { cx1[i] = nx1[i]; cx2[i] = nx2[i]; }
        }
    } else {
        for (int t = 0; t < il; ++t) {
            const float* r = xp + (size_t)t * CC;
            float x1v = r[lane];
            float x2v = (lane < 6) ? r[32 + lane] : -1e30f;
            step(x1v, x2v);
            if ((t & 7) == 7) {
                float m = fmaxf(ae, ao);
#pragma unroll
                for (int o = 16; o > 0; o >>= 1)
                    m = fmaxf(m, __shfl_xor_sync(FULLMASK, m, o));
                apply(m);
                strip();
            }
        }
    }

    // state 2*tl (even) -> lane tl+1 ; state 2*tl-1 (odd) -> lane tl
    float aev = __shfl_sync(FULLMASK, ae, tl + 1);
    float aov = __shfl_sync(FULLMASK, ao, tl);
    double ssum = (double)aev + (double)aov;

    if (ssum >= 8.673617379884035e-19 /* 2^-60 */ && ssum < 6.0e38) {
        if (lane == 0) {
            // ln alpha_end = ln ssum + Esum*ln2 + (bs - 2*il)
            // sum ln D    = ln P + Le*ln2
            double lg  = log(ssum) + (double)Esum * LN2
                       + (double)bs - 2.0 * (double)il;
            double lnD = log((double)P) + (double)Le * LN2;
            double nll = -(lg - lnD);
            if (nll > 1e8) nll = 0.0;               // zero_infinity
            g_ctc[b] = (float)(nll / (double)tl);
        }
    } else {
        float nll = ctc_fp64(xp, target, b, il, tl);
        if (lane == 0) g_ctc[b] = nll / (float)tl;
    }
}

// ---------------------------------------------------------------------------
// KL smoothing: one warp per (b,s); lane l<19 holds classes 2l, 2l+1.
// Inline (H,W,S): 3 butterflies, W derived from S (W = S + 38e-10).
// ---------------------------------------------------------------------------
__device__ __forceinline__ float kl_val(
    const float* __restrict__ x, const int* __restrict__ target,
    const int* __restrict__ tlen, const int* __restrict__ pos,
    const float* __restrict__ ms, int idx)
{
    const int lane = threadIdx.x & 31;
    const int b = idx / SS;
    const int s = idx - b * SS;

    const int tl = tlen[b];
    if (s >= tl) return 0.0f;

    const int p  = pos[b * SS + s];
    const int tg = target[b * SS + s];
    const int f  = (s == 0) ? (CC - 1) : target[b * SS + s - 1];

    const float* row = x + ((size_t)b * TT + p) * CC;
    const float* msr = ms + ((size_t)(f - 1) * 37 + (tg - 1)) * 37;

    float Ev = 0.0f, Tm = 0.0f, Sv = 0.0f;
    if (lane < 19) {
        float2 xv = ((const float2*)row)[lane];
        float se = (lane == 0) ? 0.0f : msr[2 * lane - 1];   // SLS class 2l
        float so = msr[2 * lane];                            // SLS class 2l+1
        float te = se + 1e-10f;
        float to = so + 1e-10f;
        Ev = __expf(xv.x) + __expf(xv.y);
        Tm = te * (__logf(te) - xv.x) + to * (__logf(to) - xv.y);
        Sv = se + so;
    }
#pragma unroll
    for (int o = 16; o > 0; o >>= 1) {
        Ev += __shfl_xor_sync(FULLMASK, Ev, o);
        Tm += __shfl_xor_sync(FULLMASK, Tm, o);
        Sv += __shfl_xor_sync(FULLMASK, Sv, o);
    }
    float lse = __logf(Ev);
    float W = Sv + 38e-10f;                                  // sum of t_c
    float klrow = (Tm + lse * W) * (1.0f / (float)CC);
    float L = (float)tl;
    float smooth = -expm1f(-0.05129329438755058f / L);       // 1 - 0.95^(1/L)
    return (smooth / L) * Sv * klrow;
}

// ---------------------------------------------------------------------------
// Mega-fused kernel: integrated CTC(+D) blocks + KL blocks.
// ---------------------------------------------------------------------------
__global__ void __launch_bounds__(256) mega_kernel(
    const float* __restrict__ x, const int* __restrict__ target,
    const int* __restrict__ ilen, const int* __restrict__ tlen,
    const int* __restrict__ pos, const float* __restrict__ ms)
{
    const int warp = threadIdx.x >> 5;
    if (blockIdx.x < CTC_BLOCKS) {
        ctc_body(x, target, ilen, tlen, blockIdx.x * 8 + warp);
    } else {
        const int kb = blockIdx.x - CTC_BLOCKS;
        float v = kl_val(x, target, tlen, pos, ms, kb * 8 + warp);
        __shared__ float ksum[8];
        if ((threadIdx.x & 31) == 0) ksum[warp] = v;
        __syncthreads();
        if (threadIdx.x == 0) {
            float t = 0.0f;
#pragma unroll
            for (int i = 0; i < 8; ++i) t += ksum[i];
            g_klb[kb] = t;
        }
    }
}

// ---------------------------------------------------------------------------
// Single-block deterministic final reduction.
// ---------------------------------------------------------------------------
__global__ void __launch_bounds__(1024) finalize_kernel(float* __restrict__ out)
{
    __shared__ double sm[1024];
    const int tid = threadIdx.x;
    double acc = 0.0;
    for (int i = tid; i < KL_BLOCKS; i += 1024)
        acc += (double)g_klb[i];
    for (int b = tid; b < BB; b += 1024)
        acc += (double)g_ctc[b] * (1.0 / (double)BB);
    sm[tid] = acc;
    __syncthreads();
    for (int st = 512; st > 0; st >>= 1) {
        if (tid < st) sm[tid] += sm[tid + st];
        __syncthreads();
    }
    if (tid == 0) out[0] = (float)sm[0];
}

// ---------------------------------------------------------------------------
extern "C" void kernel_launch(void* const* d_in, const int* in_sizes, int n_in,
                              void* d_out, int out_size)
{
    const float* x      = (const float*)d_in[0];   // [B,T,C] f32
    const int*   target = (const int*)d_in[1];     // [B,S]   i32
    const int*   ilen   = (const int*)d_in[2];     // [B]     i32
    const int*   tlen   = (const int*)d_in[3];     // [B]     i32
    const int*   pos    = (const int*)d_in[4];     // [B,S]   i32
    const float* ms     = (const float*)d_in[5];   // [37,37,37] f32

    mega_kernel<<<CTC_BLOCKS + KL_BLOCKS, 256>>>(x, target, ilen, tlen, pos, ms);
    finalize_kernel<<<1, 1024>>>((float*)d_out);
}

// round 13
// speedup vs baseline: 1.7205x; 1.7205x over previous
#include <cuda_runtime.h>
#include <math.h>

// Problem constants (fixed by the reference)
#define BB 4096
#define TT 200
#define CC 38
#define SS 30
#define FULLMASK 0xffffffffu
#define CTC_BLOCKS 512            // 4096 warps = 1 per sample
#define D_BLOCKS   1024           // 8192 warps = 2 per sample (100 rows each)
#define KL_BLOCKS  3840           // 30720 warps x 4 rows each = BB*SS = 122880 rows
#define LN2 0.6931471805599453

// Scratch (no cudaMalloc allowed)
__device__ double g_ctcraw[BB];     // log(unnormalized alpha_end); -1e30 = impossible
__device__ double g_d2[BB * 2];     // per-(b,halfT) sum of log2(D_t)
__device__ float  g_klb[KL_BLOCKS]; // per-block KL partial sums

// ---------------------------------------------------------------------------
// fp64 fallback (proven numerics): rerun one sample's full CTC forward with
// explicit emissions exp(x-2). Returns raw log(alpha_end). Rare.
// ---------------------------------------------------------------------------
__device__ __noinline__ double ctc_fp64(
    const float* __restrict__ xp, const int* __restrict__ target,
    int b, int il, int tl)
{
    const int lane = threadIdx.x & 31;
    int tg  = (lane < SS) ? target[b * SS + lane] : 1;
    int tgp = __shfl_up_sync(FULLMASK, tg, 1);
    const bool skip = (lane == 0 || tg != tgp);

    double ae = (lane == 0) ? 1.0 : 0.0;
    double ao = 0.0;
    for (int t = 0; t < il; ++t) {
        const float* r = xp + (size_t)t * CC;
        float pbe = __expf(r[0] - 2.0f);
        float ple = __expf(r[tg] - 2.0f);
        double op = __shfl_up_sync(FULLMASK, ao, 1);
        if (lane == 0) op = 0.0;
        double ne = (ae + op) * (double)pbe;
        double no = (ao + ae + (skip ? op : 0.0)) * (double)ple;
        ae = (lane <= 30) ? ne : 0.0;
        ao = (lane < 30) ? no : 0.0;
    }
    double aev = __shfl_sync(FULLMASK, ae, tl);
    double aov = __shfl_sync(FULLMASK, ao, tl - 1);
    double s = aev + aov;
    return (s > 0.0) ? log(s) : -1e30;
}

// ---------------------------------------------------------------------------
// CTC recursion (beta form), one warp per sample. (R9-proven, untouched.)
// beta = alpha / prod_t exp(x0_t - 2): even update is a pure ADD, odd
// multiplier is exp(x_tg - x0) -> ONE MUFU per step. Lane mapping shifted:
// lane i (1..31) holds states 2(i-1) and 2(i-1)+1; lane 0 is a constant-zero
// shfl boundary. Deferred power-of-2 renorm (stale max is exactly correct).
// Writes raw log(alpha_end) only.
// ---------------------------------------------------------------------------
__device__ __forceinline__ void ctc_body(
    const float* __restrict__ x, const int* __restrict__ target,
    const int* __restrict__ ilen, const int* __restrict__ tlen, int b)
{
    const int lane = threadIdx.x & 31;
    const bool valid = (lane >= 1 && lane <= SS);

    int tg  = valid ? target[b * SS + (lane - 1)] : 1;
    int tgp = __shfl_up_sync(FULLMASK, tg, 1);
    const float skipf = (lane == 1 || tg != tgp) ? 1.0f : 0.0f;

    const int il = ilen[b];
    const int tl = tlen[b];
    const float* xp = x + (size_t)b * TT * CC;

    float ae = (lane == 1) ? 1.0f : 0.0f;   // beta[2(lane-1)]
    float ao = 0.0f;                        // beta[2(lane-1)+1]
    int   Esum = 0;                         // true beta = stored * 2^Esum
    float bs = 0.0f, bsc = 0.0f;            // Kahan sum of (x0_t - 2)

    auto step = [&](float d) {
        float e  = __expf(d);                        // p_l / p_b
        float op = __shfl_up_sync(FULLMASK, ao, 1);  // lane0: own ao = 0
        float v  = ae + ao;                          // off-chain
        ae = ae + op;
        ao = fmaf(skipf, op, v) * e;
    };
    auto apply = [&](float m) {   // warp-uniform 2^k rescale, center 2^30
        unsigned mb = __float_as_uint(m);
        if (mb >= 0x00800000u && mb < 0x7f800000u) {
            int e = (int)(mb >> 23) - 127;
            int k = 30 - e;
            k = (k > 127) ? 127 : (k < -126 ? -126 : k);
            float sc = __uint_as_float((unsigned)(127 + k) << 23);
            ae *= sc; ao *= sc;
            Esum -= k;
        }
    };
    auto kadd = [&](float y0) {   // Kahan add into (bs, bsc)
        float y = y0 - bsc;
        float t = bs + y;
        bsc = (t - bs) - y;
        bs = t;
    };

    if (il == TT) {
        float cd[8]; float cbs;
        {
            float g = 0.0f;
#pragma unroll
            for (int i = 0; i < 8; ++i) {
                float b0 = xp[i * CC];
                float tv = xp[i * CC + tg];
                cd[i] = valid ? (tv - b0) : -1e30f;   // -1e30 kills ghost lanes
                g += b0;
            }
            cbs = g - 16.0f;
        }
        for (int g = 0; g < TT / 8; ++g) {
            float nd[8]; float nbs = 0.0f;
            if (g + 1 < TT / 8) {
                const float* np = xp + (size_t)(g + 1) * 8 * CC;
                float gsum = 0.0f;
#pragma unroll
                for (int i = 0; i < 8; ++i) {
                    float b0 = np[i * CC];
                    float tv = np[i * CC + tg];
                    nd[i] = valid ? (tv - b0) : -1e30f;
                    gsum += b0;
                }
                nbs = gsum - 16.0f;
            } else {
#pragma unroll
                for (int i = 0; i < 8; ++i) nd[i] = -1e30f;
            }
            kadd(cbs);
            step(cd[0]);
            step(cd[1]);
            step(cd[2]);
            step(cd[3]);
            // deferred max: measured here, butterfly overlaps steps 4..7
            float m = fmaxf(ae, ao);
            step(cd[4]);
            m = fmaxf(m, __shfl_xor_sync(FULLMASK, m, 16));
            step(cd[5]);
            m = fmaxf(m, __shfl_xor_sync(FULLMASK, m, 8));
            step(cd[6]);
            m = fmaxf(m, __shfl_xor_sync(FULLMASK, m, 4));
            step(cd[7]);
            m = fmaxf(m, __shfl_xor_sync(FULLMASK, m, 2));
            m = fmaxf(m, __shfl_xor_sync(FULLMASK, m, 1));
            apply(m);
#pragma unroll
            for (int i = 0; i < 8; ++i) cd[i] = nd[i];
            cbs = nbs;
        }
    } else {
        for (int t = 0; t < il; ++t) {
            const float* r = xp + (size_t)t * CC;
            float b0 = r[0];
            float d = valid ? (r[tg] - b0) : -1e30f;
            kadd(b0 - 2.0f);
            step(d);
            if ((t & 7) == 7) {
                float m = fmaxf(ae, ao);
#pragma unroll
                for (int o = 16; o > 0; o >>= 1)
                    m = fmaxf(m, __shfl_xor_sync(FULLMASK, m, o));
                apply(m);
            }
        }
    }

    // state 2*tl (even) -> lane tl+1 ; state 2*tl-1 (odd) -> lane tl
    float aev = __shfl_sync(FULLMASK, ae, tl + 1);
    float aov = __shfl_sync(FULLMASK, ao, tl);
    double ssum = (double)aev + (double)aov;

    if (ssum >= 8.673617379884035e-19 /* 2^-60 */ && ssum < 6.0e38) {
        if (lane == 0)
            g_ctcraw[b] = log(ssum) + (double)Esum * LN2 + (double)bs;
    } else {
        double raw = ctc_fp64(xp, target, b, il, tl);
        if (lane == 0) g_ctcraw[b] = raw;
    }
}

// ---------------------------------------------------------------------------
// Softmax-denominator pass, width-16, software-pipelined: warp w -> sample
// b=w/2, 100 rows. Half-warps process two consecutive rows concurrently;
// next pair's loads are issued while the current pair reduces (MLP x2).
// Running product P with exponent stripping.
// ---------------------------------------------------------------------------
__device__ __forceinline__ void d_body(
    const float* __restrict__ x, const int* __restrict__ ilen, int w)
{
    const int lane = threadIdx.x & 31;
    const int sub  = lane & 15;
    const int half = lane >> 4;
    const int b  = w >> 1;
    const int t0 = (w & 1) * 100;
    const int il = ilen[b];
    const int tend = (il < t0 + 100) ? il : (t0 + 100);

    const float* xp = x + (size_t)b * TT * CC;
    float P = 1.0f;
    int   Le = 0;
    int   it = 0;

    int t = t0;
    float2 cv = make_float2(-1e30f, -1e30f);
    float  ct = -1e30f;
    if (t + 2 <= tend) {
        const float* rb = xp + (size_t)(t + half) * CC;
        cv = ((const float2*)rb)[sub];
        ct = (sub >= 10) ? rb[22 + sub] : -1e30f;
    }
    for (; t + 2 <= tend; ++it) {
        const int tn = t + 2;
        float2 nv = make_float2(-1e30f, -1e30f);
        float  nt = -1e30f;
        if (tn + 2 <= tend) {
            const float* rb = xp + (size_t)(tn + half) * CC;
            nv = ((const float2*)rb)[sub];
            nt = (sub >= 10) ? rb[22 + sub] : -1e30f;
        }
        float e = __expf(cv.x - 2.0f) + __expf(cv.y - 2.0f) + __expf(ct - 2.0f);
#pragma unroll
        for (int o = 8; o > 0; o >>= 1)                      // within-half butterfly
            e += __shfl_xor_sync(FULLMASK, e, o);
        P *= e;                                              // own half's row sum
        if ((it & 7) == 7) {                                 // strip exponent
            unsigned pb = __float_as_uint(P);
            Le += (int)(pb >> 23) - 127;
            P = __uint_as_float((pb & 0x807fffffu) | 0x3f800000u);
        }
        cv = nv; ct = nt; t = tn;
    }
    if (t < tend) {                                          // odd remainder: half 0 only
        if (half == 0) {
            const float* rb = xp + (size_t)t * CC;
            float2 v = ((const float2*)rb)[sub];
            float tail = (sub >= 10) ? rb[22 + sub] : -1e30f;
            float e = __expf(v.x - 2.0f) + __expf(v.y - 2.0f) + __expf(tail - 2.0f);
#pragma unroll
            for (int o = 8; o > 0; o >>= 1)
                e += __shfl_xor_sync(0x0000ffffu, e, o);
            P *= e;
        }
    }
    double l2 = (double)Le + log2((double)P);
    double other = __shfl_xor_sync(FULLMASK, l2, 16);
    if (lane == 0) g_d2[w] = l2 + other;                     // sum of both halves
}

// ---------------------------------------------------------------------------
// KL smoothing (inline, R11-validated numerics): one warp per (b,s) row;
// lane l<19 holds classes 2l, 2l+1. W derived from S (W = S + 38e-10).
// ---------------------------------------------------------------------------
__device__ __forceinline__ float kl_val(
    const float* __restrict__ x, const int* __restrict__ target,
    const int* __restrict__ tlen, const int* __restrict__ pos,
    const float* __restrict__ ms, int idx)
{
    const int lane = threadIdx.x & 31;
    const int b = idx / SS;
    const int s = idx - b * SS;

    const int tl = tlen[b];
    if (s >= tl) return 0.0f;

    const int p  = pos[b * SS + s];
    const int tg = target[b * SS + s];
    const int f  = (s == 0) ? (CC - 1) : target[b * SS + s - 1];

    const float* row = x + ((size_t)b * TT + p) * CC;
    const float* msr = ms + ((size_t)(f - 1) * 37 + (tg - 1)) * 37;

    float Ev = 0.0f, Tm = 0.0f, Sv = 0.0f;
    if (lane < 19) {
        float2 xv = ((const float2*)row)[lane];
        float se = (lane == 0) ? 0.0f : msr[2 * lane - 1];   // SLS class 2l
        float so = msr[2 * lane];                            // SLS class 2l+1
        float te = se + 1e-10f;
        float to = so + 1e-10f;
        Ev = __expf(xv.x) + __expf(xv.y);
        Tm = te * (__logf(te) - xv.x) + to * (__logf(to) - xv.y);
        Sv = se + so;
    }
#pragma unroll
    for (int o = 16; o > 0; o >>= 1) {
        Ev += __shfl_xor_sync(FULLMASK, Ev, o);
        Tm += __shfl_xor_sync(FULLMASK, Tm, o);
        Sv += __shfl_xor_sync(FULLMASK, Sv, o);
    }
    float lse = __logf(Ev);
    float W = Sv + 38e-10f;                                  // sum of t_c
    float klrow = (Tm + lse * W) * (1.0f / (float)CC);
    float L = (float)tl;
    float smooth = -expm1f(-0.05129329438755058f / L);       // 1 - 0.95^(1/L)
    return (smooth / L) * Sv * klrow;
}

// ---------------------------------------------------------------------------
// Mega-fused kernel: CTC blocks + D blocks + KL blocks (4 rows per KL warp).
// KL coverage: 3840 blocks * 8 warps * 4 rows = 122880 = BB*SS. (R12's bug
// was exactly here: only 1/8 coverage.)
// ---------------------------------------------------------------------------
__global__ void __launch_bounds__(256) mega_kernel(
    const float* __restrict__ x, const int* __restrict__ target,
    const int* __restrict__ ilen, const int* __restrict__ tlen,
    const int* __restrict__ pos, const float* __restrict__ ms)
{
    const int warp = threadIdx.x >> 5;
    if (blockIdx.x < CTC_BLOCKS) {
        ctc_body(x, target, ilen, tlen, blockIdx.x * 8 + warp);
    } else if (blockIdx.x < CTC_BLOCKS + D_BLOCKS) {
        d_body(x, ilen, (blockIdx.x - CTC_BLOCKS) * 8 + warp);
    } else {
        const int kb = blockIdx.x - CTC_BLOCKS - D_BLOCKS;
        const int base = (kb * 8 + warp) * 4;
        float v = 0.0f;
#pragma unroll
        for (int r = 0; r < 4; ++r)
            v += kl_val(x, target, tlen, pos, ms, base + r);
        __shared__ float ksum[8];
        if ((threadIdx.x & 31) == 0) ksum[warp] = v;
        __syncthreads();
        if (threadIdx.x == 0) {
            float t = 0.0f;
#pragma unroll
            for (int i = 0; i < 8; ++i) t += ksum[i];
            g_klb[kb] = t;
        }
    }
}

// ---------------------------------------------------------------------------
// Single-block deterministic final reduction + per-sample nll finalize.
// ---------------------------------------------------------------------------
__global__ void __launch_bounds__(1024) finalize_kernel(
    const int* __restrict__ tlen, float* __restrict__ out)
{
    __shared__ double sm[1024];
    const int tid = threadIdx.x;
    double acc = 0.0;
#pragma unroll 4
    for (int i = tid; i < KL_BLOCKS; i += 1024)
        acc += (double)g_klb[i];
#pragma unroll 4
    for (int b = tid; b < BB; b += 1024) {
        double lnD = (g_d2[2 * b] + g_d2[2 * b + 1]) * LN2;
        double nll = -(g_ctcraw[b] - lnD);
        if (nll > 1e8) nll = 0.0;                            // zero_infinity
        acc += (nll / (double)tlen[b]) * (1.0 / (double)BB);
    }
    sm[tid] = acc;
    __syncthreads();
    for (int st = 512; st > 0; st >>= 1) {
        if (tid < st) sm[tid] += sm[tid + st];
        __syncthreads();
    }
    if (tid == 0) out[0] = (float)sm[0];
}

// ---------------------------------------------------------------------------
extern "C" void kernel_launch(void* const* d_in, const int* in_sizes, int n_in,
                              void* d_out, int out_size)
{
    const float* x      = (const float*)d_in[0];   // [B,T,C] f32
    const int*   target = (const int*)d_in[1];     // [B,S]   i32
    const int*   ilen   = (const int*)d_in[2];     // [B]     i32
    const int*   tlen   = (const int*)d_in[3];     // [B]     i32
    const int*   pos    = (const int*)d_in[4];     // [B,S]   i32
    const float* ms     = (const float*)d_in[5];   // [37,37,37] f32

    mega_kernel<<<CTC_BLOCKS + D_BLOCKS + KL_BLOCKS, 256>>>(
        x, target, ilen, tlen, pos, ms);
    finalize_kernel<<<1, 1024>>>(tlen, (float*)d_out);
}